// round 11
// baseline (speedup 1.0000x reference)
#include <cuda_runtime.h>
#include <cuda_fp16.h>
#include <cstdint>

// Problem constants
#define NB    32
#define CLOC  512
#define HW2   196
#define NHW   6272
#define DGLB  2048
#define HIDN  256
#define EPSC  1e-10f

// Scratch (device globals; no allocation allowed)
__device__ float    g_hloc[NHW * HIDN];      // 6.4 MB
__device__ float    g_hglb[NB * HIDN];
__device__ float    g_scores[NB * NHW];      // 0.8 MB
// W2 in mma-fragment order: pair id = ((ks*4 + nw)*8 + nt)*32 + lane
__device__ uint2    g_W2f[16 * 4 * 8 * 32];  // 128 KB

// ---------------------------------------------------------------------------
// helpers
// ---------------------------------------------------------------------------
__device__ __forceinline__ void mma16(float* c, const uint32_t* a,
                                      uint32_t b0, uint32_t b1) {
    asm volatile(
        "mma.sync.aligned.m16n8k16.row.col.f32.f16.f16.f32 "
        "{%0,%1,%2,%3}, {%4,%5,%6,%7}, {%8,%9}, {%0,%1,%2,%3};"
        : "+f"(c[0]), "+f"(c[1]), "+f"(c[2]), "+f"(c[3])
        : "r"(a[0]), "r"(a[1]), "r"(a[2]), "r"(a[3]), "r"(b0), "r"(b1));
}
__device__ __forceinline__ uint32_t smem_u32(const void* p) {
    uint32_t a;
    asm("{ .reg .u64 t; cvta.to.shared.u64 t, %1; cvt.u32.u64 %0, t; }" : "=r"(a) : "l"(p));
    return a;
}
__device__ __forceinline__ void cpa16(uint32_t dst, const void* src) {
    asm volatile("cp.async.ca.shared.global [%0], [%1], 16;" :: "r"(dst), "l"(src));
}
#define CPA_COMMIT() asm volatile("cp.async.commit_group;" ::: "memory")

// ---------------------------------------------------------------------------
// prep (256-thread blocks):
//   blocks 0..255   -> h_glb: block = (i = bx>>3, o-chunk = (bx&7)*32), K-split x8
//   blocks 256..263 -> pack W2 into fragment order (fp16 pairs)
// ---------------------------------------------------------------------------
__global__ __launch_bounds__(256) void prep_kernel(const float* __restrict__ gf,
                                                   const float* __restrict__ W1,
                                                   const float* __restrict__ b1,
                                                   const float* __restrict__ W2) {
    const int tid = threadIdx.x;
    if (blockIdx.x < 256) {
        __shared__ float red[256];
        const int i   = blockIdx.x >> 3;
        const int o0  = (blockIdx.x & 7) * 32;
        const int o   = o0 + (tid & 31);
        const int kq  = tid >> 5;                 // 0..7
        const float* g = gf + i * DGLB + kq * 256;
        const float* w = W1 + (long)(kq * 256) * HIDN + o;
        float s0 = 0.f, s1 = 0.f;
        #pragma unroll 8
        for (int k = 0; k < 256; k += 2) {
            s0 += g[k]     * w[(long)k * HIDN];
            s1 += g[k + 1] * w[(long)(k + 1) * HIDN];
        }
        red[tid] = s0 + s1;
        __syncthreads();
        if (tid < 32) {
            float s = 0.f;
            #pragma unroll
            for (int q = 0; q < 8; q++) s += red[q * 32 + tid];
            g_hglb[i * HIDN + o0 + tid] = s + b1[o0 + tid];
        }
    } else {
        // fragment-order pack: 16384 pairs, 8 per thread
        const int pid0 = ((blockIdx.x - 256) * 256 + tid) * 8;
        #pragma unroll
        for (int q = 0; q < 8; q++) {
            int id   = pid0 + q;
            int lane = id & 31;
            int nt   = (id >> 5) & 7;
            int nwp  = (id >> 8) & 3;
            int ks   = id >> 10;
            int gq   = lane >> 2, tg = lane & 3;
            int n    = nwp * 64 + nt * 8 + gq;
            int k0   = ks * 16 + 2 * tg;
            __half2 w0 = __floats2half2_rn(W2[(long)k0 * HIDN + n],
                                           W2[(long)(k0 + 1) * HIDN + n]);
            __half2 w1 = __floats2half2_rn(W2[(long)(k0 + 8) * HIDN + n],
                                           W2[(long)(k0 + 9) * HIDN + n]);
            g_W2f[id] = make_uint2(*(uint32_t*)&w0, *(uint32_t*)&w1);
        }
    }
}

// ---------------------------------------------------------------------------
// h_loc = lf @ W1[D:]  (6272 x 512 @ 512 x 256), fp32 SGEMM (exact)
// ---------------------------------------------------------------------------
__global__ __launch_bounds__(256) void hloc_kernel(const float* __restrict__ LF,
                                                   const float* __restrict__ W1loc) {
    __shared__ float As[64][33];
    __shared__ float Bs[32][256];
    const int j0  = blockIdx.x * 64;
    const int tid = threadIdx.x;
    const int tm  = tid >> 5;
    const int tn  = tid & 31;
    const int am  = tid & 63;
    const int akq = tid >> 6;
    const int j   = j0 + am;
    const int n_  = j / HW2;
    const int pos = j % HW2;
    const long abase = (long)n_ * CLOC * HW2 + pos;
    const int bn4 = tid & 63;
    const int bkq = tid >> 6;

    float acc[8][8];
    #pragma unroll
    for (int a = 0; a < 8; a++)
        #pragma unroll
        for (int b = 0; b < 8; b++) acc[a][b] = 0.f;

    for (int kc = 0; kc < CLOC; kc += 32) {
        #pragma unroll
        for (int r = 0; r < 8; r++) {
            int k = akq * 8 + r;
            As[am][k] = LF[abase + (long)(kc + k) * HW2];
        }
        #pragma unroll
        for (int r = 0; r < 8; r++) {
            int k = bkq + 4 * r;
            *(float4*)&Bs[k][bn4 * 4] = *(const float4*)&W1loc[(kc + k) * HIDN + bn4 * 4];
        }
        __syncthreads();
        #pragma unroll
        for (int k = 0; k < 32; k++) {
            float a[8];
            #pragma unroll
            for (int im = 0; im < 8; im++) a[im] = As[tm * 8 + im][k];
            float4 b0 = *(float4*)&Bs[k][tn * 4];
            float4 b1 = *(float4*)&Bs[k][128 + tn * 4];
            #pragma unroll
            for (int im = 0; im < 8; im++) {
                acc[im][0] += a[im] * b0.x; acc[im][1] += a[im] * b0.y;
                acc[im][2] += a[im] * b0.z; acc[im][3] += a[im] * b0.w;
                acc[im][4] += a[im] * b1.x; acc[im][5] += a[im] * b1.y;
                acc[im][6] += a[im] * b1.z; acc[im][7] += a[im] * b1.w;
            }
        }
        __syncthreads();
    }
    #pragma unroll
    for (int im = 0; im < 8; im++) {
        int m = j0 + tm * 8 + im;
        float4 v0 = make_float4(acc[im][0], acc[im][1], acc[im][2], acc[im][3]);
        float4 v1 = make_float4(acc[im][4], acc[im][5], acc[im][6], acc[im][7]);
        *(float4*)&g_hloc[m * HIDN + tn * 4]       = v0;
        *(float4*)&g_hloc[m * HIDN + 128 + tn * 4] = v1;
    }
}

// ---------------------------------------------------------------------------
// score kernel: fp16 m16n8k16 mma.sync, 512 threads / 16 warps (4m x 4n).
// B (all 128 KB, fragment order) resident in smem, issued as 4 cp.async
// commit-groups at entry with staged wait_group per chunk. A double-buffered
// with LDG prefetch during mma.
// ---------------------------------------------------------------------------
#define AS_STRH  72                                 // halves per A row (36 words)
#define AS_BYTES (128 * AS_STRH * 2)                // 18432
#define BCHUNK   32768
#define AS_OFF   0
#define BS_OFF   (2 * AS_BYTES)                     // 36864
#define B2_OFF   (BS_OFF + 4 * BCHUNK)              // 167936
#define W3_OFF   (B2_OFF + 1024)
#define RED_OFF  (W3_OFF + 1024)
#define SM_TOTAL (RED_OFF + 128 * 4 * 4)            // 172032

__global__ __launch_bounds__(512, 1) void score_mma(const float* __restrict__ b2,
                                                    const float* __restrict__ W3,
                                                    const float* __restrict__ b3p) {
    extern __shared__ char smem[];
    float* b2s = (float*)(smem + B2_OFF);
    float* w3s = (float*)(smem + W3_OFF);
    float* red = (float*)(smem + RED_OFF);
    const uint32_t sbase = smem_u32(smem);

    const int tid = threadIdx.x;
    const int wid = tid >> 5, lid = tid & 31;
    const int g   = lid >> 2, tig = lid & 3;
    const int j0  = blockIdx.x * 128;
    const int i   = blockIdx.y;
    const int m0w = (wid & 3) * 32;
    const int nw  = wid >> 2;
    const int n0w = nw * 64;

    // ---- issue ALL B loads up front: 4 commit-groups, one per 64-k chunk ----
    {
        const char* bsrc = (const char*)g_W2f;
        #pragma unroll
        for (int cg = 0; cg < 4; cg++) {
            #pragma unroll
            for (int r = 0; r < 4; r++) {
                int off = cg * BCHUNK + (tid + r * 512) * 16;
                cpa16(sbase + BS_OFF + off, bsrc + off);
            }
            CPA_COMMIT();
        }
    }

    if (tid < 256) { b2s[tid] = b2[tid]; w3s[tid] = W3[tid]; }

    // fill-phase thread mappings
    const int k4   = tid & 15;                       // A: halves [k4*4 .. k4*4+3]
    const int mrow = tid >> 4;                       // A rows: mrow + r*32, r<4

    const float* hl = g_hloc + (long)j0 * HIDN;
    const float* gb = g_hglb + i * HIDN;

    float acc[2][8][4];
    #pragma unroll
    for (int mt = 0; mt < 2; mt++)
        #pragma unroll
        for (int nt = 0; nt < 8; nt++)
            #pragma unroll
            for (int q = 0; q < 4; q++) acc[mt][nt][q] = 0.f;

    // ---- initial A build: chunk 0 into buffer 0 (overlaps B arrival) ----
    {
        float4 gv = *(const float4*)(gb + k4 * 4);
        __half* As0 = (__half*)(smem + AS_OFF);
        #pragma unroll
        for (int r = 0; r < 4; r++) {
            int m = mrow + r * 32;
            float4 v = *(const float4*)(hl + (long)m * HIDN + k4 * 4);
            __half2 h01 = __floats2half2_rn(fmaxf(v.x + gv.x, 0.f), fmaxf(v.y + gv.y, 0.f));
            __half2 h23 = __floats2half2_rn(fmaxf(v.z + gv.z, 0.f), fmaxf(v.w + gv.w, 0.f));
            uint2 pk = make_uint2(*(uint32_t*)&h01, *(uint32_t*)&h23);
            *(uint2*)(As0 + m * AS_STRH + k4 * 4) = pk;
        }
        asm volatile("cp.async.wait_group 3;" ::: "memory");   // B chunk 0 ready
        __syncthreads();
    }

    const uint2* BsP = (const uint2*)(smem + BS_OFF);

    for (int c = 0; c < 4; c++) {
        const int pb = c & 1, nb = pb ^ 1;
        const uint32_t* AsU = (const uint32_t*)(smem + AS_OFF + pb * AS_BYTES);

        // ---- prefetch next chunk's A into registers ----
        float4 areg[4];
        float4 gvn;
        if (c < 3) {
            const int kb = (c + 1) * 64;
            gvn = *(const float4*)(gb + kb + k4 * 4);
            #pragma unroll
            for (int r = 0; r < 4; r++) {
                int m = mrow + r * 32;
                areg[r] = *(const float4*)(hl + (long)m * HIDN + kb + k4 * 4);
            }
        }

        // ---- mma phase: 4 k16 steps, B indexed by global kstep ----
        #pragma unroll
        for (int kk = 0; kk < 4; kk++) {
            const int kw = kk * 8;
            const int ks = c * 4 + kk;
            uint32_t a[2][4];
            #pragma unroll
            for (int mt = 0; mt < 2; mt++) {
                int mr = m0w + mt * 16 + g;
                a[mt][0] = AsU[mr * 36 + kw + tig];
                a[mt][1] = AsU[(mr + 8) * 36 + kw + tig];
                a[mt][2] = AsU[mr * 36 + kw + tig + 4];
                a[mt][3] = AsU[(mr + 8) * 36 + kw + tig + 4];
            }
            #pragma unroll
            for (int nt = 0; nt < 8; nt++) {
                uint2 bw = BsP[((ks * 4 + nw) * 8 + nt) * 32 + lid];
                mma16(acc[0][nt], a[0], bw.x, bw.y);
                mma16(acc[1][nt], a[1], bw.x, bw.y);
            }
        }

        // ---- store prefetched A; staged B wait; barrier ----
        if (c < 3) {
            __half* AsN = (__half*)(smem + AS_OFF + nb * AS_BYTES);
            #pragma unroll
            for (int r = 0; r < 4; r++) {
                int m = mrow + r * 32;
                __half2 h01 = __floats2half2_rn(fmaxf(areg[r].x + gvn.x, 0.f),
                                                fmaxf(areg[r].y + gvn.y, 0.f));
                __half2 h23 = __floats2half2_rn(fmaxf(areg[r].z + gvn.z, 0.f),
                                                fmaxf(areg[r].w + gvn.w, 0.f));
                uint2 pk = make_uint2(*(uint32_t*)&h01, *(uint32_t*)&h23);
                *(uint2*)(AsN + m * AS_STRH + k4 * 4) = pk;
            }
            if (c == 0)      asm volatile("cp.async.wait_group 2;" ::: "memory");
            else if (c == 1) asm volatile("cp.async.wait_group 1;" ::: "memory");
            else             asm volatile("cp.async.wait_group 0;" ::: "memory");
            __syncthreads();
        }
    }

    // ---- epilogue: relu(acc + b2) . W3, reduce n across lanes/warps ----
    #pragma unroll
    for (int mt = 0; mt < 2; mt++) {
        float s0 = 0.f, s1 = 0.f;
        #pragma unroll
        for (int nt = 0; nt < 8; nt++) {
            int n = n0w + nt * 8 + 2 * tig;
            float w0 = w3s[n], w1 = w3s[n + 1];
            float c0 = b2s[n], c1 = b2s[n + 1];
            s0 += fmaxf(acc[mt][nt][0] + c0, 0.f) * w0
                + fmaxf(acc[mt][nt][1] + c1, 0.f) * w1;
            s1 += fmaxf(acc[mt][nt][2] + c0, 0.f) * w0
                + fmaxf(acc[mt][nt][3] + c1, 0.f) * w1;
        }
        s0 += __shfl_xor_sync(0xffffffffu, s0, 1);
        s0 += __shfl_xor_sync(0xffffffffu, s0, 2);
        s1 += __shfl_xor_sync(0xffffffffu, s1, 1);
        s1 += __shfl_xor_sync(0xffffffffu, s1, 2);
        if (tig == 0) {
            red[(m0w + mt * 16 + g) * 4 + nw]     = s0;
            red[(m0w + mt * 16 + g + 8) * 4 + nw] = s1;
        }
    }
    __syncthreads();
    if (tid < 128) {
        float s = red[tid * 4] + red[tid * 4 + 1] + red[tid * 4 + 2] + red[tid * 4 + 3];
        g_scores[i * NHW + j0 + tid] = s + b3p[0];
    }
}

// ---------------------------------------------------------------------------
// finalize: register-cached row + shuffle reductions (2-stage)
// ---------------------------------------------------------------------------
__global__ __launch_bounds__(1024) void finalize_kernel(float* __restrict__ out) {
    const int i    = blockIdx.x;
    const int tid  = threadIdx.x;
    const int wid  = tid >> 5, lane = tid & 31;
    __shared__ float sred[32];
    __shared__ float sbc[2];
    const float* row = g_scores + i * NHW;

    float v[7];
    const bool has7 = (tid < NHW - 6 * 1024);        // tid < 128
    float mx = -1e30f;
    #pragma unroll
    for (int k = 0; k < 6; k++) {
        v[k] = row[tid + k * 1024];
        mx = fmaxf(mx, v[k]);
    }
    if (has7) { v[6] = row[tid + 6 * 1024]; mx = fmaxf(mx, v[6]); }

    #pragma unroll
    for (int off = 16; off; off >>= 1)
        mx = fmaxf(mx, __shfl_xor_sync(0xffffffffu, mx, off));
    if (lane == 0) sred[wid] = mx;
    __syncthreads();
    if (wid == 0) {
        float m = sred[lane];
        #pragma unroll
        for (int off = 16; off; off >>= 1)
            m = fmaxf(m, __shfl_xor_sync(0xffffffffu, m, off));
        if (lane == 0) sbc[0] = m;
    }
    __syncthreads();
    mx = sbc[0];

    const int lo = i * HW2, hi = lo + HW2;
    float sum = 0.f;
    #pragma unroll
    for (int k = 0; k < 6; k++) {
        int jj = tid + k * 1024;
        if (jj < lo || jj >= hi) sum += __expf(v[k] - mx);
    }
    if (has7) {
        int jj = tid + 6 * 1024;
        if (jj < lo || jj >= hi) sum += __expf(v[6] - mx);
    }
    #pragma unroll
    for (int off = 16; off; off >>= 1)
        sum += __shfl_xor_sync(0xffffffffu, sum, off);
    if (lane == 0) sred[wid] = sum;
    __syncthreads();
    if (wid == 0) {
        float s = sred[lane];
        #pragma unroll
        for (int off = 16; off; off >>= 1)
            s += __shfl_xor_sync(0xffffffffu, s, off);
        if (lane == 0) sbc[1] = s;
    }
    __syncthreads();

    const float neg_mean = sbc[1] / (float)(NHW - HW2) + EPSC;
    const float lg = __logf(neg_mean);

    for (int p = tid; p < HW2; p += 1024)
        out[i * HW2 + p] = row[lo + p] - mx - lg;
}

// ---------------------------------------------------------------------------
extern "C" void kernel_launch(void* const* d_in, const int* in_sizes, int n_in,
                              void* d_out, int out_size) {
    const float* LF = (const float*)d_in[0];
    const float* GF = (const float*)d_in[1];
    const float* W1 = (const float*)d_in[2];
    const float* b1 = (const float*)d_in[3];
    const float* W2 = (const float*)d_in[4];
    const float* b2 = (const float*)d_in[5];
    const float* W3 = (const float*)d_in[6];
    const float* b3 = (const float*)d_in[7];
    float* out = (float*)d_out;

    cudaFuncSetAttribute(score_mma, cudaFuncAttributeMaxDynamicSharedMemorySize, SM_TOTAL);

    prep_kernel<<<264, 256>>>(GF, W1, b1, W2);
    hloc_kernel<<<NHW / 64, 256>>>(LF, W1 + (long)DGLB * HIDN);
    score_mma<<<dim3(NHW / 128, NB), 512, SM_TOTAL>>>(b2, W3, b3);
    finalize_kernel<<<NB, 1024>>>(out);
}

// round 12
// speedup vs baseline: 1.6615x; 1.6615x over previous
#include <cuda_runtime.h>
#include <cuda_fp16.h>
#include <cstdint>

// Problem constants
#define NB    32
#define CLOC  512
#define HW2   196
#define NHW   6272
#define DGLB  2048
#define HIDN  256
#define EPSC  1e-10f
#define NJT   49                    // j-tiles of 128
#define NTILE (NJT * NB)            // 1568 tiles
#define NCTA  148                   // persistent CTAs

// Scratch (device globals; no allocation allowed)
__device__ float    g_hloc[NHW * HIDN];      // 6.4 MB
__device__ float    g_hglb[NB * HIDN];
__device__ float    g_scores[NB * NHW];      // 0.8 MB
// W2 in mma-fragment order: pair id = ((ks*4 + nw)*8 + nt)*32 + lane
__device__ uint2    g_W2f[16 * 4 * 8 * 32];  // 128 KB

// ---------------------------------------------------------------------------
// helpers
// ---------------------------------------------------------------------------
__device__ __forceinline__ void mma16(float* c, const uint32_t* a,
                                      uint32_t b0, uint32_t b1) {
    asm volatile(
        "mma.sync.aligned.m16n8k16.row.col.f32.f16.f16.f32 "
        "{%0,%1,%2,%3}, {%4,%5,%6,%7}, {%8,%9}, {%0,%1,%2,%3};"
        : "+f"(c[0]), "+f"(c[1]), "+f"(c[2]), "+f"(c[3])
        : "r"(a[0]), "r"(a[1]), "r"(a[2]), "r"(a[3]), "r"(b0), "r"(b1));
}
__device__ __forceinline__ uint32_t smem_u32(const void* p) {
    uint32_t a;
    asm("{ .reg .u64 t; cvta.to.shared.u64 t, %1; cvt.u32.u64 %0, t; }" : "=r"(a) : "l"(p));
    return a;
}
__device__ __forceinline__ void cpa16(uint32_t dst, const void* src) {
    asm volatile("cp.async.ca.shared.global [%0], [%1], 16;" :: "r"(dst), "l"(src));
}
#define CPA_COMMIT() asm volatile("cp.async.commit_group;" ::: "memory")

// ---------------------------------------------------------------------------
// prep (256-thread blocks):
//   blocks 0..255   -> h_glb: block = (i = bx>>3, o-chunk = (bx&7)*32), K-split x8
//   blocks 256..263 -> pack W2 into fragment order (fp16 pairs)
// ---------------------------------------------------------------------------
__global__ __launch_bounds__(256) void prep_kernel(const float* __restrict__ gf,
                                                   const float* __restrict__ W1,
                                                   const float* __restrict__ b1,
                                                   const float* __restrict__ W2) {
    const int tid = threadIdx.x;
    if (blockIdx.x < 256) {
        __shared__ float red[256];
        const int i   = blockIdx.x >> 3;
        const int o0  = (blockIdx.x & 7) * 32;
        const int o   = o0 + (tid & 31);
        const int kq  = tid >> 5;                 // 0..7
        const float* g = gf + i * DGLB + kq * 256;
        const float* w = W1 + (long)(kq * 256) * HIDN + o;
        float s0 = 0.f, s1 = 0.f;
        #pragma unroll 8
        for (int k = 0; k < 256; k += 2) {
            s0 += g[k]     * w[(long)k * HIDN];
            s1 += g[k + 1] * w[(long)(k + 1) * HIDN];
        }
        red[tid] = s0 + s1;
        __syncthreads();
        if (tid < 32) {
            float s = 0.f;
            #pragma unroll
            for (int q = 0; q < 8; q++) s += red[q * 32 + tid];
            g_hglb[i * HIDN + o0 + tid] = s + b1[o0 + tid];
        }
    } else {
        // fragment-order pack: 16384 pairs, 8 per thread
        const int pid0 = ((blockIdx.x - 256) * 256 + tid) * 8;
        #pragma unroll
        for (int q = 0; q < 8; q++) {
            int id   = pid0 + q;
            int lane = id & 31;
            int nt   = (id >> 5) & 7;
            int nwp  = (id >> 8) & 3;
            int ks   = id >> 10;
            int gq   = lane >> 2, tg = lane & 3;
            int n    = nwp * 64 + nt * 8 + gq;
            int k0   = ks * 16 + 2 * tg;
            __half2 w0 = __floats2half2_rn(W2[(long)k0 * HIDN + n],
                                           W2[(long)(k0 + 1) * HIDN + n]);
            __half2 w1 = __floats2half2_rn(W2[(long)(k0 + 8) * HIDN + n],
                                           W2[(long)(k0 + 9) * HIDN + n]);
            g_W2f[id] = make_uint2(*(uint32_t*)&w0, *(uint32_t*)&w1);
        }
    }
}

// ---------------------------------------------------------------------------
// h_loc = lf @ W1[D:]  (6272 x 512 @ 512 x 256), fp32 SGEMM (exact)
// ---------------------------------------------------------------------------
__global__ __launch_bounds__(256) void hloc_kernel(const float* __restrict__ LF,
                                                   const float* __restrict__ W1loc) {
    __shared__ float As[64][33];
    __shared__ float Bs[32][256];
    const int j0  = blockIdx.x * 64;
    const int tid = threadIdx.x;
    const int tm  = tid >> 5;
    const int tn  = tid & 31;
    const int am  = tid & 63;
    const int akq = tid >> 6;
    const int j   = j0 + am;
    const int n_  = j / HW2;
    const int pos = j % HW2;
    const long abase = (long)n_ * CLOC * HW2 + pos;
    const int bn4 = tid & 63;
    const int bkq = tid >> 6;

    float acc[8][8];
    #pragma unroll
    for (int a = 0; a < 8; a++)
        #pragma unroll
        for (int b = 0; b < 8; b++) acc[a][b] = 0.f;

    for (int kc = 0; kc < CLOC; kc += 32) {
        #pragma unroll
        for (int r = 0; r < 8; r++) {
            int k = akq * 8 + r;
            As[am][k] = LF[abase + (long)(kc + k) * HW2];
        }
        #pragma unroll
        for (int r = 0; r < 8; r++) {
            int k = bkq + 4 * r;
            *(float4*)&Bs[k][bn4 * 4] = *(const float4*)&W1loc[(kc + k) * HIDN + bn4 * 4];
        }
        __syncthreads();
        #pragma unroll
        for (int k = 0; k < 32; k++) {
            float a[8];
            #pragma unroll
            for (int im = 0; im < 8; im++) a[im] = As[tm * 8 + im][k];
            float4 b0 = *(float4*)&Bs[k][tn * 4];
            float4 b1 = *(float4*)&Bs[k][128 + tn * 4];
            #pragma unroll
            for (int im = 0; im < 8; im++) {
                acc[im][0] += a[im] * b0.x; acc[im][1] += a[im] * b0.y;
                acc[im][2] += a[im] * b0.z; acc[im][3] += a[im] * b0.w;
                acc[im][4] += a[im] * b1.x; acc[im][5] += a[im] * b1.y;
                acc[im][6] += a[im] * b1.z; acc[im][7] += a[im] * b1.w;
            }
        }
        __syncthreads();
    }
    #pragma unroll
    for (int im = 0; im < 8; im++) {
        int m = j0 + tm * 8 + im;
        float4 v0 = make_float4(acc[im][0], acc[im][1], acc[im][2], acc[im][3]);
        float4 v1 = make_float4(acc[im][4], acc[im][5], acc[im][6], acc[im][7]);
        *(float4*)&g_hloc[m * HIDN + tn * 4]       = v0;
        *(float4*)&g_hloc[m * HIDN + 128 + tn * 4] = v1;
    }
}

// ---------------------------------------------------------------------------
// PERSISTENT score kernel: 148 CTAs, 512 threads / 16 warps (4m x 4n).
// Each CTA loops over tiles t = bid, bid+148, ... (tile -> i = t/49, jt = t%49).
// B (128 KB fragment-packed W2) loaded ONCE per CTA; A double-buffered
// continuously across chunk AND tile boundaries with register prefetch.
// ---------------------------------------------------------------------------
#define AS_STRH  72                                 // halves per A row (36 words)
#define AS_BYTES (128 * AS_STRH * 2)                // 18432
#define BCHUNK   32768
#define AS_OFF   0
#define BS_OFF   (2 * AS_BYTES)                     // 36864
#define B2_OFF   (BS_OFF + 4 * BCHUNK)              // 167936
#define W3_OFF   (B2_OFF + 1024)
#define RED_OFF  (W3_OFF + 1024)
#define SM_TOTAL (RED_OFF + 128 * 4 * 4)            // 172032

__global__ __launch_bounds__(512, 1) void score_mma(const float* __restrict__ b2,
                                                    const float* __restrict__ W3,
                                                    const float* __restrict__ b3p) {
    extern __shared__ char smem[];
    float* b2s = (float*)(smem + B2_OFF);
    float* w3s = (float*)(smem + W3_OFF);
    float* red = (float*)(smem + RED_OFF);
    const uint32_t sbase = smem_u32(smem);

    const int tid = threadIdx.x;
    const int wid = tid >> 5, lid = tid & 31;
    const int g   = lid >> 2, tig = lid & 3;
    const int m0w = (wid & 3) * 32;
    const int nw  = wid >> 2;
    const int n0w = nw * 64;

    // ---- B: issue ALL 128 KB once, 4 commit-groups (amortized over ~10 tiles)
    {
        const char* bsrc = (const char*)g_W2f;
        #pragma unroll
        for (int cg = 0; cg < 4; cg++) {
            #pragma unroll
            for (int r = 0; r < 4; r++) {
                int off = cg * BCHUNK + (tid + r * 512) * 16;
                cpa16(sbase + BS_OFF + off, bsrc + off);
            }
            CPA_COMMIT();
        }
    }

    if (tid < 256) { b2s[tid] = b2[tid]; w3s[tid] = W3[tid]; }
    const float b3v = b3p[0];

    // fill-phase thread mappings
    const int k4   = tid & 15;                       // A: halves [k4*4 .. k4*4+3]
    const int mrow = tid >> 4;                       // A rows: mrow + r*32, r<4

    float acc[2][8][4];
    #pragma unroll
    for (int mt = 0; mt < 2; mt++)
        #pragma unroll
        for (int nt = 0; nt < 8; nt++)
            #pragma unroll
            for (int q = 0; q < 4; q++) acc[mt][nt][q] = 0.f;

    // ---- prologue: build A chunk 0 of first tile into buffer 0 (overlaps B) --
    {
        const int t0 = blockIdx.x;
        const float* hl = g_hloc + (size_t)(t0 % NJT) * 128 * HIDN;
        const float* gb = g_hglb + (t0 / NJT) * HIDN;
        float4 gv = *(const float4*)(gb + k4 * 4);
        __half* As0 = (__half*)(smem + AS_OFF);
        #pragma unroll
        for (int r = 0; r < 4; r++) {
            int m = mrow + r * 32;
            float4 v = *(const float4*)(hl + (size_t)m * HIDN + k4 * 4);
            __half2 h01 = __floats2half2_rn(fmaxf(v.x + gv.x, 0.f), fmaxf(v.y + gv.y, 0.f));
            __half2 h23 = __floats2half2_rn(fmaxf(v.z + gv.z, 0.f), fmaxf(v.w + gv.w, 0.f));
            *(uint2*)(As0 + m * AS_STRH + k4 * 4) =
                make_uint2(*(uint32_t*)&h01, *(uint32_t*)&h23);
        }
        asm volatile("cp.async.wait_group 3;" ::: "memory");   // B chunk 0 ready
        __syncthreads();
    }

    const uint2* BsP = (const uint2*)(smem + BS_OFF);
    int cg = 0;                                      // global chunk counter

    for (int t = blockIdx.x; t < NTILE; t += NCTA) {
        const int jt = t % NJT, ii = t / NJT;

        for (int c = 0; c < 4; c++) {
            const int pb = cg & 1, nb = pb ^ 1;
            const uint32_t* AsU = (const uint32_t*)(smem + AS_OFF + pb * AS_BYTES);

            // ---- prefetch next chunk's A into registers (may cross tiles) ----
            const bool hn = (c < 3) || (t + NCTA < NTILE);
            float4 areg[4];
            float4 gvn;
            if (hn) {
                const int t2 = (c < 3) ? t : t + NCTA;
                const int c2 = (c < 3) ? c + 1 : 0;
                const float* hl2 = g_hloc + (size_t)(t2 % NJT) * 128 * HIDN;
                const float* gb2 = g_hglb + (t2 / NJT) * HIDN;
                const int kb2 = c2 * 64;
                gvn = *(const float4*)(gb2 + kb2 + k4 * 4);
                #pragma unroll
                for (int r = 0; r < 4; r++) {
                    int m = mrow + r * 32;
                    areg[r] = *(const float4*)(hl2 + (size_t)m * HIDN + kb2 + k4 * 4);
                }
            }

            // ---- mma: 4 k16 steps; B indexed by global kstep ----
            #pragma unroll
            for (int kk = 0; kk < 4; kk++) {
                const int kw = kk * 8;
                const int ks = c * 4 + kk;
                uint32_t a[2][4];
                #pragma unroll
                for (int mt = 0; mt < 2; mt++) {
                    int mr = m0w + mt * 16 + g;
                    a[mt][0] = AsU[mr * 36 + kw + tig];
                    a[mt][1] = AsU[(mr + 8) * 36 + kw + tig];
                    a[mt][2] = AsU[mr * 36 + kw + tig + 4];
                    a[mt][3] = AsU[(mr + 8) * 36 + kw + tig + 4];
                }
                #pragma unroll
                for (int nt = 0; nt < 8; nt++) {
                    uint2 bw = BsP[((ks * 4 + nw) * 8 + nt) * 32 + lid];
                    mma16(acc[0][nt], a[0], bw.x, bw.y);
                    mma16(acc[1][nt], a[1], bw.x, bw.y);
                }
            }

            // ---- store prefetched A into the other buffer; sync ----
            if (hn) {
                __half* AsN = (__half*)(smem + AS_OFF + nb * AS_BYTES);
                #pragma unroll
                for (int r = 0; r < 4; r++) {
                    int m = mrow + r * 32;
                    __half2 h01 = __floats2half2_rn(fmaxf(areg[r].x + gvn.x, 0.f),
                                                    fmaxf(areg[r].y + gvn.y, 0.f));
                    __half2 h23 = __floats2half2_rn(fmaxf(areg[r].z + gvn.z, 0.f),
                                                    fmaxf(areg[r].w + gvn.w, 0.f));
                    *(uint2*)(AsN + m * AS_STRH + k4 * 4) =
                        make_uint2(*(uint32_t*)&h01, *(uint32_t*)&h23);
                }
            }
            // staged B waits cover only the first tile's chunks
            if (cg == 0)      asm volatile("cp.async.wait_group 2;" ::: "memory");
            else if (cg == 1) asm volatile("cp.async.wait_group 1;" ::: "memory");
            else if (cg == 2) asm volatile("cp.async.wait_group 0;" ::: "memory");
            __syncthreads();
            cg++;
        }

        // ---- per-tile epilogue: relu(acc + b2) . W3 -> scores row ----
        #pragma unroll
        for (int mt = 0; mt < 2; mt++) {
            float s0 = 0.f, s1 = 0.f;
            #pragma unroll
            for (int nt = 0; nt < 8; nt++) {
                int n = n0w + nt * 8 + 2 * tig;
                float w0 = w3s[n], w1 = w3s[n + 1];
                float c0 = b2s[n], c1 = b2s[n + 1];
                s0 += fmaxf(acc[mt][nt][0] + c0, 0.f) * w0
                    + fmaxf(acc[mt][nt][1] + c1, 0.f) * w1;
                s1 += fmaxf(acc[mt][nt][2] + c0, 0.f) * w0
                    + fmaxf(acc[mt][nt][3] + c1, 0.f) * w1;
            }
            s0 += __shfl_xor_sync(0xffffffffu, s0, 1);
            s0 += __shfl_xor_sync(0xffffffffu, s0, 2);
            s1 += __shfl_xor_sync(0xffffffffu, s1, 1);
            s1 += __shfl_xor_sync(0xffffffffu, s1, 2);
            if (tig == 0) {
                red[(m0w + mt * 16 + g) * 4 + nw]     = s0;
                red[(m0w + mt * 16 + g + 8) * 4 + nw] = s1;
            }
        }
        #pragma unroll
        for (int mt = 0; mt < 2; mt++)
            #pragma unroll
            for (int nt = 0; nt < 8; nt++)
                #pragma unroll
                for (int q = 0; q < 4; q++) acc[mt][nt][q] = 0.f;
        __syncthreads();
        if (tid < 128) {
            float s = red[tid * 4] + red[tid * 4 + 1] + red[tid * 4 + 2] + red[tid * 4 + 3];
            g_scores[ii * NHW + jt * 128 + tid] = s + b3v;
        }
        __syncthreads();
    }
}

// ---------------------------------------------------------------------------
// finalize: register-cached row + shuffle reductions (2-stage)
// ---------------------------------------------------------------------------
__global__ __launch_bounds__(1024) void finalize_kernel(float* __restrict__ out) {
    const int i    = blockIdx.x;
    const int tid  = threadIdx.x;
    const int wid  = tid >> 5, lane = tid & 31;
    __shared__ float sred[32];
    __shared__ float sbc[2];
    const float* row = g_scores + i * NHW;

    float v[7];
    const bool has7 = (tid < NHW - 6 * 1024);        // tid < 128
    float mx = -1e30f;
    #pragma unroll
    for (int k = 0; k < 6; k++) {
        v[k] = row[tid + k * 1024];
        mx = fmaxf(mx, v[k]);
    }
    if (has7) { v[6] = row[tid + 6 * 1024]; mx = fmaxf(mx, v[6]); }

    #pragma unroll
    for (int off = 16; off; off >>= 1)
        mx = fmaxf(mx, __shfl_xor_sync(0xffffffffu, mx, off));
    if (lane == 0) sred[wid] = mx;
    __syncthreads();
    if (wid == 0) {
        float m = sred[lane];
        #pragma unroll
        for (int off = 16; off; off >>= 1)
            m = fmaxf(m, __shfl_xor_sync(0xffffffffu, m, off));
        if (lane == 0) sbc[0] = m;
    }
    __syncthreads();
    mx = sbc[0];

    const int lo = i * HW2, hi = lo + HW2;
    float sum = 0.f;
    #pragma unroll
    for (int k = 0; k < 6; k++) {
        int jj = tid + k * 1024;
        if (jj < lo || jj >= hi) sum += __expf(v[k] - mx);
    }
    if (has7) {
        int jj = tid + 6 * 1024;
        if (jj < lo || jj >= hi) sum += __expf(v[6] - mx);
    }
    #pragma unroll
    for (int off = 16; off; off >>= 1)
        sum += __shfl_xor_sync(0xffffffffu, sum, off);
    if (lane == 0) sred[wid] = sum;
    __syncthreads();
    if (wid == 0) {
        float s = sred[lane];
        #pragma unroll
        for (int off = 16; off; off >>= 1)
            s += __shfl_xor_sync(0xffffffffu, s, off);
        if (lane == 0) sbc[1] = s;
    }
    __syncthreads();

    const float neg_mean = sbc[1] / (float)(NHW - HW2) + EPSC;
    const float lg = __logf(neg_mean);

    for (int p = tid; p < HW2; p += 1024)
        out[i * HW2 + p] = row[lo + p] - mx - lg;
}

// ---------------------------------------------------------------------------
extern "C" void kernel_launch(void* const* d_in, const int* in_sizes, int n_in,
                              void* d_out, int out_size) {
    const float* LF = (const float*)d_in[0];
    const float* GF = (const float*)d_in[1];
    const float* W1 = (const float*)d_in[2];
    const float* b1 = (const float*)d_in[3];
    const float* W2 = (const float*)d_in[4];
    const float* b2 = (const float*)d_in[5];
    const float* W3 = (const float*)d_in[6];
    const float* b3 = (const float*)d_in[7];
    float* out = (float*)d_out;

    cudaFuncSetAttribute(score_mma, cudaFuncAttributeMaxDynamicSharedMemorySize, SM_TOTAL);

    prep_kernel<<<264, 256>>>(GF, W1, b1, W2);
    hloc_kernel<<<NHW / 64, 256>>>(LF, W1 + (long)DGLB * HIDN);
    score_mma<<<NCTA, 512, SM_TOTAL>>>(b2, W3, b3);
    finalize_kernel<<<NB, 1024>>>(out);
}

// round 13
// speedup vs baseline: 2.2166x; 1.3341x over previous
#include <cuda_runtime.h>
#include <cuda_fp16.h>
#include <cstdint>

// Problem constants
#define NB    32
#define CLOC  512
#define HW2   196
#define NHW   6272
#define DGLB  2048
#define HIDN  256
#define EPSC  1e-10f
#define NJT   49                    // j-tiles of 128
#define NTILE (NJT * NB)            // 1568 tiles
#define NCTA  148                   // persistent CTAs

// Scratch (device globals; no allocation allowed)
__device__ float    g_hloc[NHW * HIDN];      // 6.4 MB
__device__ float    g_hglb[NB * HIDN];
__device__ float    g_scores[NB * NHW];      // 0.8 MB
// W2 in mma-fragment order: pair id = ((ks*4 + nw)*8 + nt)*32 + lane
__device__ uint2    g_W2f[16 * 4 * 8 * 32];  // 128 KB

// ---------------------------------------------------------------------------
// helpers
// ---------------------------------------------------------------------------
__device__ __forceinline__ float tf32r(float x) {
    float y;
    asm("cvt.rna.tf32.f32 %0, %1;" : "=f"(y) : "f"(x));
    return y;
}
__device__ __forceinline__ void mma16(float* c, const uint32_t* a,
                                      uint32_t b0, uint32_t b1) {
    asm volatile(
        "mma.sync.aligned.m16n8k16.row.col.f32.f16.f16.f32 "
        "{%0,%1,%2,%3}, {%4,%5,%6,%7}, {%8,%9}, {%0,%1,%2,%3};"
        : "+f"(c[0]), "+f"(c[1]), "+f"(c[2]), "+f"(c[3])
        : "r"(a[0]), "r"(a[1]), "r"(a[2]), "r"(a[3]), "r"(b0), "r"(b1));
}
__device__ __forceinline__ void mma8(float* c, const uint32_t* a,
                                     uint32_t b0, uint32_t b1) {
    asm volatile(
        "mma.sync.aligned.m16n8k8.row.col.f32.tf32.tf32.f32 "
        "{%0,%1,%2,%3}, {%4,%5,%6,%7}, {%8,%9}, {%0,%1,%2,%3};"
        : "+f"(c[0]), "+f"(c[1]), "+f"(c[2]), "+f"(c[3])
        : "r"(a[0]), "r"(a[1]), "r"(a[2]), "r"(a[3]), "r"(b0), "r"(b1));
}
__device__ __forceinline__ uint32_t smem_u32(const void* p) {
    uint32_t a;
    asm("{ .reg .u64 t; cvta.to.shared.u64 t, %1; cvt.u32.u64 %0, t; }" : "=r"(a) : "l"(p));
    return a;
}
__device__ __forceinline__ void cpa16(uint32_t dst, const void* src) {
    asm volatile("cp.async.ca.shared.global [%0], [%1], 16;" :: "r"(dst), "l"(src));
}
#define CPA_COMMIT() asm volatile("cp.async.commit_group;" ::: "memory")

// ---------------------------------------------------------------------------
// pre_kernel (256-thread blocks, dynamic smem):
//   blocks 0..97    -> hloc_tc: h_loc = lf @ W1[D:] via tf32 mma (RNA-rounded)
//   blocks 98..353  -> h_glb: (i = (bx-98)>>3, o-chunk = ((bx-98)&7)*32), K/8
//   blocks 354..361 -> pack W2 into fp16 fragment order
// hloc_tc tile: BM=64, BN=256, BK=32 x 16 chunks, double-buffered via regs.
// 8 warps = 2m x 4n; warp tile 32m x 64n; acc[2][8][4].
// ---------------------------------------------------------------------------
#define HAS_W   (64 * 36)                    // A buffer words (stride 36)
#define HBS_W   (32 * 264)                   // B buffer words (stride 264)
#define PRE_SMEM ((2 * HAS_W + 2 * HBS_W) * 4)   // 86016 bytes

__global__ __launch_bounds__(256) void pre_kernel(const float* __restrict__ LF,
                                                  const float* __restrict__ W1loc,
                                                  const float* __restrict__ gf,
                                                  const float* __restrict__ W1,
                                                  const float* __restrict__ b1,
                                                  const float* __restrict__ W2) {
    extern __shared__ float dsm[];
    const int tid = threadIdx.x;
    const int bx  = blockIdx.x;

    if (bx < 98) {
        // ================= hloc via tf32 mma =================
        float* As = dsm;                     // 2 buffers of HAS_W
        float* Bs = dsm + 2 * HAS_W;         // 2 buffers of HBS_W
        const int wid = tid >> 5, lid = tid & 31;
        const int g   = lid >> 2, tig = lid & 3;
        const int m0w = (wid & 1) * 32;
        const int n0w = (wid >> 1) * 64;
        const int j0  = bx * 64;

        // fill maps
        const int am  = tid & 63;            // A row
        const int akq = tid >> 6;            // A k-quarter
        const int j   = j0 + am;
        const int n_  = j / HW2;
        const int pos = j % HW2;
        const size_t abase = (size_t)n_ * CLOC * HW2 + pos;
        const int bn4 = tid & 63;            // B n/4
        const int bk  = tid >> 6;            // B k row base

        float acc[2][8][4];
        #pragma unroll
        for (int mt = 0; mt < 2; mt++)
            #pragma unroll
            for (int nt = 0; nt < 8; nt++)
                #pragma unroll
                for (int q = 0; q < 4; q++) acc[mt][nt][q] = 0.f;

        // build chunk 0 into buffer 0
        #pragma unroll
        for (int r = 0; r < 8; r++) {
            int k = akq * 8 + r;
            As[am * 36 + k] = tf32r(LF[abase + (size_t)k * HW2]);
        }
        #pragma unroll
        for (int r = 0; r < 8; r++) {
            int k = bk + 4 * r;
            float4 v = *(const float4*)&W1loc[(size_t)k * HIDN + bn4 * 4];
            float* d = Bs + k * 264 + bn4 * 4;
            d[0] = tf32r(v.x); d[1] = tf32r(v.y); d[2] = tf32r(v.z); d[3] = tf32r(v.w);
        }
        __syncthreads();

        for (int c = 0; c < 16; c++) {
            const int pb = c & 1, nb = pb ^ 1;
            const uint32_t* AsU = (const uint32_t*)(As + pb * HAS_W);
            const uint32_t* BsU = (const uint32_t*)(Bs + pb * HBS_W);

            // prefetch next chunk to registers
            float aR[8];
            float4 bR[8];
            if (c < 15) {
                const int kb = (c + 1) * 32;
                #pragma unroll
                for (int r = 0; r < 8; r++)
                    aR[r] = LF[abase + (size_t)(kb + akq * 8 + r) * HW2];
                #pragma unroll
                for (int r = 0; r < 8; r++)
                    bR[r] = *(const float4*)&W1loc[(size_t)(kb + bk + 4 * r) * HIDN + bn4 * 4];
            }

            // mma: 4 k8 steps
            #pragma unroll
            for (int k8 = 0; k8 < 4; k8++) {
                const int kk = k8 * 8;
                uint32_t a[2][4];
                #pragma unroll
                for (int mt = 0; mt < 2; mt++) {
                    int mr = m0w + mt * 16 + g;
                    a[mt][0] = AsU[mr * 36 + kk + tig];
                    a[mt][1] = AsU[(mr + 8) * 36 + kk + tig];
                    a[mt][2] = AsU[mr * 36 + kk + tig + 4];
                    a[mt][3] = AsU[(mr + 8) * 36 + kk + tig + 4];
                }
                #pragma unroll
                for (int nt = 0; nt < 8; nt++) {
                    int nc = n0w + nt * 8 + g;
                    uint32_t b0 = BsU[(kk + tig) * 264 + nc];
                    uint32_t b1 = BsU[(kk + tig + 4) * 264 + nc];
                    mma8(acc[0][nt], a[0], b0, b1);
                    mma8(acc[1][nt], a[1], b0, b1);
                }
            }

            // store prefetched chunk into other buffer
            if (c < 15) {
                float* AsN = As + nb * HAS_W;
                float* BsN = Bs + nb * HBS_W;
                #pragma unroll
                for (int r = 0; r < 8; r++)
                    AsN[am * 36 + akq * 8 + r] = tf32r(aR[r]);
                #pragma unroll
                for (int r = 0; r < 8; r++) {
                    float* d = BsN + (bk + 4 * r) * 264 + bn4 * 4;
                    d[0] = tf32r(bR[r].x); d[1] = tf32r(bR[r].y);
                    d[2] = tf32r(bR[r].z); d[3] = tf32r(bR[r].w);
                }
                __syncthreads();
            }
        }

        // epilogue: write fp32 h_loc
        #pragma unroll
        for (int mt = 0; mt < 2; mt++) {
            int row0 = j0 + m0w + mt * 16 + g;
            #pragma unroll
            for (int nt = 0; nt < 8; nt++) {
                int ncol = n0w + nt * 8 + 2 * tig;
                *(float2*)&g_hloc[(size_t)row0 * HIDN + ncol] =
                    make_float2(acc[mt][nt][0], acc[mt][nt][1]);
                *(float2*)&g_hloc[(size_t)(row0 + 8) * HIDN + ncol] =
                    make_float2(acc[mt][nt][2], acc[mt][nt][3]);
            }
        }
    } else if (bx < 354) {
        // ================= h_glb =================
        float* red = dsm;                    // 256 floats
        const int bb  = bx - 98;
        const int i   = bb >> 3;
        const int o0  = (bb & 7) * 32;
        const int o   = o0 + (tid & 31);
        const int kq  = tid >> 5;            // 0..7
        const float* g = gf + i * DGLB + kq * 256;
        const float* w = W1 + (size_t)(kq * 256) * HIDN + o;
        float s0 = 0.f, s1 = 0.f;
        #pragma unroll 8
        for (int k = 0; k < 256; k += 2) {
            s0 += g[k]     * w[(size_t)k * HIDN];
            s1 += g[k + 1] * w[(size_t)(k + 1) * HIDN];
        }
        red[tid] = s0 + s1;
        __syncthreads();
        if (tid < 32) {
            float s = 0.f;
            #pragma unroll
            for (int q = 0; q < 8; q++) s += red[q * 32 + tid];
            g_hglb[i * HIDN + o0 + tid] = s + b1[o0 + tid];
        }
    } else {
        // ================= W2 fragment pack =================
        const int pid0 = ((bx - 354) * 256 + tid) * 8;
        #pragma unroll
        for (int q = 0; q < 8; q++) {
            int id   = pid0 + q;
            int lane = id & 31;
            int nt   = (id >> 5) & 7;
            int nwp  = (id >> 8) & 3;
            int ks   = id >> 10;
            int gq   = lane >> 2, tg = lane & 3;
            int n    = nwp * 64 + nt * 8 + gq;
            int k0   = ks * 16 + 2 * tg;
            __half2 w0 = __floats2half2_rn(W2[(size_t)k0 * HIDN + n],
                                           W2[(size_t)(k0 + 1) * HIDN + n]);
            __half2 w1 = __floats2half2_rn(W2[(size_t)(k0 + 8) * HIDN + n],
                                           W2[(size_t)(k0 + 9) * HIDN + n]);
            g_W2f[id] = make_uint2(*(uint32_t*)&w0, *(uint32_t*)&w1);
        }
    }
}

// ---------------------------------------------------------------------------
// PERSISTENT score kernel (UNCHANGED from R12): 148 CTAs, 512 threads.
// ---------------------------------------------------------------------------
#define AS_STRH  72                                 // halves per A row (36 words)
#define AS_BYTES (128 * AS_STRH * 2)                // 18432
#define BCHUNK   32768
#define AS_OFF   0
#define BS_OFF   (2 * AS_BYTES)                     // 36864
#define B2_OFF   (BS_OFF + 4 * BCHUNK)              // 167936
#define W3_OFF   (B2_OFF + 1024)
#define RED_OFF  (W3_OFF + 1024)
#define SM_TOTAL (RED_OFF + 128 * 4 * 4)            // 172032

__global__ __launch_bounds__(512, 1) void score_mma(const float* __restrict__ b2,
                                                    const float* __restrict__ W3,
                                                    const float* __restrict__ b3p) {
    extern __shared__ char smem[];
    float* b2s = (float*)(smem + B2_OFF);
    float* w3s = (float*)(smem + W3_OFF);
    float* red = (float*)(smem + RED_OFF);
    const uint32_t sbase = smem_u32(smem);

    const int tid = threadIdx.x;
    const int wid = tid >> 5, lid = tid & 31;
    const int g   = lid >> 2, tig = lid & 3;
    const int m0w = (wid & 3) * 32;
    const int nw  = wid >> 2;
    const int n0w = nw * 64;

    {
        const char* bsrc = (const char*)g_W2f;
        #pragma unroll
        for (int cg2 = 0; cg2 < 4; cg2++) {
            #pragma unroll
            for (int r = 0; r < 4; r++) {
                int off = cg2 * BCHUNK + (tid + r * 512) * 16;
                cpa16(sbase + BS_OFF + off, bsrc + off);
            }
            CPA_COMMIT();
        }
    }

    if (tid < 256) { b2s[tid] = b2[tid]; w3s[tid] = W3[tid]; }
    const float b3v = b3p[0];

    const int k4   = tid & 15;
    const int mrow = tid >> 4;

    float acc[2][8][4];
    #pragma unroll
    for (int mt = 0; mt < 2; mt++)
        #pragma unroll
        for (int nt = 0; nt < 8; nt++)
            #pragma unroll
            for (int q = 0; q < 4; q++) acc[mt][nt][q] = 0.f;

    {
        const int t0 = blockIdx.x;
        const float* hl = g_hloc + (size_t)(t0 % NJT) * 128 * HIDN;
        const float* gb = g_hglb + (t0 / NJT) * HIDN;
        float4 gv = *(const float4*)(gb + k4 * 4);
        __half* As0 = (__half*)(smem + AS_OFF);
        #pragma unroll
        for (int r = 0; r < 4; r++) {
            int m = mrow + r * 32;
            float4 v = *(const float4*)(hl + (size_t)m * HIDN + k4 * 4);
            __half2 h01 = __floats2half2_rn(fmaxf(v.x + gv.x, 0.f), fmaxf(v.y + gv.y, 0.f));
            __half2 h23 = __floats2half2_rn(fmaxf(v.z + gv.z, 0.f), fmaxf(v.w + gv.w, 0.f));
            *(uint2*)(As0 + m * AS_STRH + k4 * 4) =
                make_uint2(*(uint32_t*)&h01, *(uint32_t*)&h23);
        }
        asm volatile("cp.async.wait_group 3;" ::: "memory");
        __syncthreads();
    }

    const uint2* BsP = (const uint2*)(smem + BS_OFF);
    int cg = 0;

    for (int t = blockIdx.x; t < NTILE; t += NCTA) {
        const int jt = t % NJT, ii = t / NJT;

        for (int c = 0; c < 4; c++) {
            const int pb = cg & 1, nb = pb ^ 1;
            const uint32_t* AsU = (const uint32_t*)(smem + AS_OFF + pb * AS_BYTES);

            const bool hn = (c < 3) || (t + NCTA < NTILE);
            float4 areg[4];
            float4 gvn;
            if (hn) {
                const int t2 = (c < 3) ? t : t + NCTA;
                const int c2 = (c < 3) ? c + 1 : 0;
                const float* hl2 = g_hloc + (size_t)(t2 % NJT) * 128 * HIDN;
                const float* gb2 = g_hglb + (t2 / NJT) * HIDN;
                const int kb2 = c2 * 64;
                gvn = *(const float4*)(gb2 + kb2 + k4 * 4);
                #pragma unroll
                for (int r = 0; r < 4; r++) {
                    int m = mrow + r * 32;
                    areg[r] = *(const float4*)(hl2 + (size_t)m * HIDN + kb2 + k4 * 4);
                }
            }

            #pragma unroll
            for (int kk = 0; kk < 4; kk++) {
                const int kw = kk * 8;
                const int ks = c * 4 + kk;
                uint32_t a[2][4];
                #pragma unroll
                for (int mt = 0; mt < 2; mt++) {
                    int mr = m0w + mt * 16 + g;
                    a[mt][0] = AsU[mr * 36 + kw + tig];
                    a[mt][1] = AsU[(mr + 8) * 36 + kw + tig];
                    a[mt][2] = AsU[mr * 36 + kw + tig + 4];
                    a[mt][3] = AsU[(mr + 8) * 36 + kw + tig + 4];
                }
                #pragma unroll
                for (int nt = 0; nt < 8; nt++) {
                    uint2 bw = BsP[((ks * 4 + nw) * 8 + nt) * 32 + lid];
                    mma16(acc[0][nt], a[0], bw.x, bw.y);
                    mma16(acc[1][nt], a[1], bw.x, bw.y);
                }
            }

            if (hn) {
                __half* AsN = (__half*)(smem + AS_OFF + nb * AS_BYTES);
                #pragma unroll
                for (int r = 0; r < 4; r++) {
                    int m = mrow + r * 32;
                    __half2 h01 = __floats2half2_rn(fmaxf(areg[r].x + gvn.x, 0.f),
                                                    fmaxf(areg[r].y + gvn.y, 0.f));
                    __half2 h23 = __floats2half2_rn(fmaxf(areg[r].z + gvn.z, 0.f),
                                                    fmaxf(areg[r].w + gvn.w, 0.f));
                    *(uint2*)(AsN + m * AS_STRH + k4 * 4) =
                        make_uint2(*(uint32_t*)&h01, *(uint32_t*)&h23);
                }
            }
            if (cg == 0)      asm volatile("cp.async.wait_group 2;" ::: "memory");
            else if (cg == 1) asm volatile("cp.async.wait_group 1;" ::: "memory");
            else if (cg == 2) asm volatile("cp.async.wait_group 0;" ::: "memory");
            __syncthreads();
            cg++;
        }

        #pragma unroll
        for (int mt = 0; mt < 2; mt++) {
            float s0 = 0.f, s1 = 0.f;
            #pragma unroll
            for (int nt = 0; nt < 8; nt++) {
                int n = n0w + nt * 8 + 2 * tig;
                float w0 = w3s[n], w1 = w3s[n + 1];
                float c0 = b2s[n], c1 = b2s[n + 1];
                s0 += fmaxf(acc[mt][nt][0] + c0, 0.f) * w0
                    + fmaxf(acc[mt][nt][1] + c1, 0.f) * w1;
                s1 += fmaxf(acc[mt][nt][2] + c0, 0.f) * w0
                    + fmaxf(acc[mt][nt][3] + c1, 0.f) * w1;
            }
            s0 += __shfl_xor_sync(0xffffffffu, s0, 1);
            s0 += __shfl_xor_sync(0xffffffffu, s0, 2);
            s1 += __shfl_xor_sync(0xffffffffu, s1, 1);
            s1 += __shfl_xor_sync(0xffffffffu, s1, 2);
            if (tig == 0) {
                red[(m0w + mt * 16 + g) * 4 + nw]     = s0;
                red[(m0w + mt * 16 + g + 8) * 4 + nw] = s1;
            }
        }
        #pragma unroll
        for (int mt = 0; mt < 2; mt++)
            #pragma unroll
            for (int nt = 0; nt < 8; nt++)
                #pragma unroll
                for (int q = 0; q < 4; q++) acc[mt][nt][q] = 0.f;
        __syncthreads();
        if (tid < 128) {
            float s = red[tid * 4] + red[tid * 4 + 1] + red[tid * 4 + 2] + red[tid * 4 + 3];
            g_scores[ii * NHW + jt * 128 + tid] = s + b3v;
        }
        __syncthreads();
    }
}

// ---------------------------------------------------------------------------
// finalize: register-cached row + shuffle reductions (2-stage)
// ---------------------------------------------------------------------------
__global__ __launch_bounds__(1024) void finalize_kernel(float* __restrict__ out) {
    const int i    = blockIdx.x;
    const int tid  = threadIdx.x;
    const int wid  = tid >> 5, lane = tid & 31;
    __shared__ float sred[32];
    __shared__ float sbc[2];
    const float* row = g_scores + i * NHW;

    float v[7];
    const bool has7 = (tid < NHW - 6 * 1024);
    float mx = -1e30f;
    #pragma unroll
    for (int k = 0; k < 6; k++) {
        v[k] = row[tid + k * 1024];
        mx = fmaxf(mx, v[k]);
    }
    if (has7) { v[6] = row[tid + 6 * 1024]; mx = fmaxf(mx, v[6]); }

    #pragma unroll
    for (int off = 16; off; off >>= 1)
        mx = fmaxf(mx, __shfl_xor_sync(0xffffffffu, mx, off));
    if (lane == 0) sred[wid] = mx;
    __syncthreads();
    if (wid == 0) {
        float m = sred[lane];
        #pragma unroll
        for (int off = 16; off; off >>= 1)
            m = fmaxf(m, __shfl_xor_sync(0xffffffffu, m, off));
        if (lane == 0) sbc[0] = m;
    }
    __syncthreads();
    mx = sbc[0];

    const int lo = i * HW2, hi = lo + HW2;
    float sum = 0.f;
    #pragma unroll
    for (int k = 0; k < 6; k++) {
        int jj = tid + k * 1024;
        if (jj < lo || jj >= hi) sum += __expf(v[k] - mx);
    }
    if (has7) {
        int jj = tid + 6 * 1024;
        if (jj < lo || jj >= hi) sum += __expf(v[6] - mx);
    }
    #pragma unroll
    for (int off = 16; off; off >>= 1)
        sum += __shfl_xor_sync(0xffffffffu, sum, off);
    if (lane == 0) sred[wid] = sum;
    __syncthreads();
    if (wid == 0) {
        float s = sred[lane];
        #pragma unroll
        for (int off = 16; off; off >>= 1)
            s += __shfl_xor_sync(0xffffffffu, s, off);
        if (lane == 0) sbc[1] = s;
    }
    __syncthreads();

    const float neg_mean = sbc[1] / (float)(NHW - HW2) + EPSC;
    const float lg = __logf(neg_mean);

    for (int p = tid; p < HW2; p += 1024)
        out[i * HW2 + p] = row[lo + p] - mx - lg;
}

// ---------------------------------------------------------------------------
extern "C" void kernel_launch(void* const* d_in, const int* in_sizes, int n_in,
                              void* d_out, int out_size) {
    const float* LF = (const float*)d_in[0];
    const float* GF = (const float*)d_in[1];
    const float* W1 = (const float*)d_in[2];
    const float* b1 = (const float*)d_in[3];
    const float* W2 = (const float*)d_in[4];
    const float* b2 = (const float*)d_in[5];
    const float* W3 = (const float*)d_in[6];
    const float* b3 = (const float*)d_in[7];
    float* out = (float*)d_out;

    cudaFuncSetAttribute(pre_kernel, cudaFuncAttributeMaxDynamicSharedMemorySize, PRE_SMEM);
    cudaFuncSetAttribute(score_mma, cudaFuncAttributeMaxDynamicSharedMemorySize, SM_TOTAL);

    pre_kernel<<<362, 256, PRE_SMEM>>>(LF, W1 + (size_t)DGLB * HIDN, GF, W1, b1, W2);
    score_mma<<<NCTA, 512, SM_TOTAL>>>(b2, W3, b3);
    finalize_kernel<<<NB, 1024>>>(out);
}

// round 14
// speedup vs baseline: 2.3399x; 1.0556x over previous
#include <cuda_runtime.h>
#include <cuda_fp16.h>
#include <cstdint>

// Problem constants
#define NB    32
#define CLOC  512
#define HW2   196
#define NHW   6272
#define DGLB  2048
#define HIDN  256
#define EPSC  1e-10f
#define NJT   49                    // j-tiles of 128
#define NTILE (NJT * NB)            // 1568 tiles
#define NCTA  148                   // persistent CTAs

// Scratch (device globals; no allocation allowed)
__device__ float    g_hloc[NHW * HIDN];      // 6.4 MB
__device__ float    g_hglb[NB * HIDN];
__device__ float    g_scores[NB * NHW];      // 0.8 MB
// W2 in mma-fragment order: pair id = ((ks*4 + nw)*8 + nt)*32 + lane
__device__ uint2    g_W2f[16 * 4 * 8 * 32];  // 128 KB

// ---------------------------------------------------------------------------
// helpers
// ---------------------------------------------------------------------------
__device__ __forceinline__ void mma16(float* c, const uint32_t* a,
                                      uint32_t b0, uint32_t b1) {
    asm volatile(
        "mma.sync.aligned.m16n8k16.row.col.f32.f16.f16.f32 "
        "{%0,%1,%2,%3}, {%4,%5,%6,%7}, {%8,%9}, {%0,%1,%2,%3};"
        : "+f"(c[0]), "+f"(c[1]), "+f"(c[2]), "+f"(c[3])
        : "r"(a[0]), "r"(a[1]), "r"(a[2]), "r"(a[3]), "r"(b0), "r"(b1));
}
__device__ __forceinline__ uint32_t smem_u32(const void* p) {
    uint32_t a;
    asm("{ .reg .u64 t; cvta.to.shared.u64 t, %1; cvt.u32.u64 %0, t; }" : "=r"(a) : "l"(p));
    return a;
}
__device__ __forceinline__ void cpa16(uint32_t dst, const void* src) {
    asm volatile("cp.async.ca.shared.global [%0], [%1], 16;" :: "r"(dst), "l"(src));
}
#define CPA_COMMIT() asm volatile("cp.async.commit_group;" ::: "memory")

// ---------------------------------------------------------------------------
// pre_kernel (256-thread blocks, dynamic smem), grid = 460:
//   blocks 0..195   -> hloc fp16 mma: BM=32, BN=256, BK=32 x 16 chunks
//   blocks 196..451 -> h_glb: (i = bb>>3, o-chunk = (bb&7)*32), K/8
//   blocks 452..459 -> pack W2 into fp16 fragment order
// hloc: 8 warps, warp = 32m x 32n (n0 = wid*32); acc[2][4][4] = 32 regs.
// A smem: 32 rows x 40 halves (20 words, bank-perfect) x2 buffers.
// B smem: [k2][n] half2, 16 k2-rows x 264 words x2 buffers.
// ---------------------------------------------------------------------------
#define HA_HW   40                           // A stride in halves (20 words)
#define HA_B    (32 * HA_HW * 2)             // 2560 bytes per A buffer
#define HB_W    264                          // B stride in words
#define HB_B    (16 * HB_W * 4)              // 16896 bytes per B buffer
#define PRE_SMEM (2 * HA_B + 2 * HB_B)       // 38912 bytes

__global__ __launch_bounds__(256) void pre_kernel(const float* __restrict__ LF,
                                                  const float* __restrict__ W1loc,
                                                  const float* __restrict__ gf,
                                                  const float* __restrict__ W1,
                                                  const float* __restrict__ b1,
                                                  const float* __restrict__ W2) {
    extern __shared__ float dsm[];
    const int tid = threadIdx.x;
    const int bx  = blockIdx.x;

    if (bx < 196) {
        // ================= hloc via fp16 mma =================
        char* base = (char*)dsm;
        const int wid = tid >> 5, lid = tid & 31;
        const int g   = lid >> 2, tig = lid & 3;
        const int n0w = wid * 32;
        const int j0  = bx * 32;

        // A build map: row = tid&31, kq = tid>>5 (k = kq*4, 4 halves)
        const int arow = tid & 31;
        const int akq  = tid >> 5;
        const int j    = j0 + arow;
        const int n_   = j / HW2;
        const int pos  = j % HW2;
        const size_t abase = (size_t)n_ * CLOC * HW2 + pos;
        // B build map: bn4 = tid&63 (n = bn4*4), bkb = tid>>6 (k2 rows bkb+4r)
        const int bn4 = tid & 63;
        const int bkb = tid >> 6;

        float acc[2][4][4];
        #pragma unroll
        for (int mt = 0; mt < 2; mt++)
            #pragma unroll
            for (int nt = 0; nt < 4; nt++)
                #pragma unroll
                for (int q = 0; q < 4; q++) acc[mt][nt][q] = 0.f;

        // ---- build chunk 0 into buffer 0 ----
        {
            __half* A0 = (__half*)base;
            uint32_t* B0 = (uint32_t*)(base + 2 * HA_B);
            float f0 = LF[abase + (size_t)(akq * 4 + 0) * HW2];
            float f1 = LF[abase + (size_t)(akq * 4 + 1) * HW2];
            float f2 = LF[abase + (size_t)(akq * 4 + 2) * HW2];
            float f3 = LF[abase + (size_t)(akq * 4 + 3) * HW2];
            __half2 h01 = __floats2half2_rn(f0, f1);
            __half2 h23 = __floats2half2_rn(f2, f3);
            *(uint2*)(A0 + arow * HA_HW + akq * 4) =
                make_uint2(*(uint32_t*)&h01, *(uint32_t*)&h23);
            #pragma unroll
            for (int r = 0; r < 4; r++) {
                int k2 = bkb + r * 4;                 // local k2 row
                float4 va = *(const float4*)&W1loc[(size_t)(2 * k2)     * HIDN + bn4 * 4];
                float4 vb = *(const float4*)&W1loc[(size_t)(2 * k2 + 1) * HIDN + bn4 * 4];
                __half2 p0 = __floats2half2_rn(va.x, vb.x);
                __half2 p1 = __floats2half2_rn(va.y, vb.y);
                __half2 p2 = __floats2half2_rn(va.z, vb.z);
                __half2 p3 = __floats2half2_rn(va.w, vb.w);
                uint32_t* d = B0 + k2 * HB_W + bn4 * 4;
                d[0] = *(uint32_t*)&p0; d[1] = *(uint32_t*)&p1;
                d[2] = *(uint32_t*)&p2; d[3] = *(uint32_t*)&p3;
            }
        }
        __syncthreads();

        for (int c = 0; c < 16; c++) {
            const int pb = c & 1, nb = pb ^ 1;
            const uint32_t* AsU = (const uint32_t*)(base + pb * HA_B);
            const uint32_t* BsU = (const uint32_t*)(base + 2 * HA_B + pb * HB_B);

            // prefetch next chunk to registers
            float aR[4];
            float4 bRa[4], bRb[4];
            if (c < 15) {
                const int kb = (c + 1) * 32;
                #pragma unroll
                for (int q = 0; q < 4; q++)
                    aR[q] = LF[abase + (size_t)(kb + akq * 4 + q) * HW2];
                #pragma unroll
                for (int r = 0; r < 4; r++) {
                    int gk = kb + 2 * (bkb + r * 4);
                    bRa[r] = *(const float4*)&W1loc[(size_t)gk       * HIDN + bn4 * 4];
                    bRb[r] = *(const float4*)&W1loc[(size_t)(gk + 1) * HIDN + bn4 * 4];
                }
            }

            // mma: 2 k16 steps
            #pragma unroll
            for (int s = 0; s < 2; s++) {
                const int kw  = s * 8;
                uint32_t a[2][4];
                #pragma unroll
                for (int mt = 0; mt < 2; mt++) {
                    int mr = mt * 16 + g;
                    a[mt][0] = AsU[mr * 20 + kw + tig];
                    a[mt][1] = AsU[(mr + 8) * 20 + kw + tig];
                    a[mt][2] = AsU[mr * 20 + kw + tig + 4];
                    a[mt][3] = AsU[(mr + 8) * 20 + kw + tig + 4];
                }
                #pragma unroll
                for (int nt = 0; nt < 4; nt++) {
                    int nc = n0w + nt * 8 + g;
                    uint32_t b0 = BsU[(s * 8 + tig) * HB_W + nc];
                    uint32_t b1 = BsU[(s * 8 + tig + 4) * HB_W + nc];
                    mma16(acc[0][nt], a[0], b0, b1);
                    mma16(acc[1][nt], a[1], b0, b1);
                }
            }

            // store prefetched chunk into other buffer
            if (c < 15) {
                __half* AN = (__half*)(base + nb * HA_B);
                uint32_t* BN = (uint32_t*)(base + 2 * HA_B + nb * HB_B);
                __half2 h01 = __floats2half2_rn(aR[0], aR[1]);
                __half2 h23 = __floats2half2_rn(aR[2], aR[3]);
                *(uint2*)(AN + arow * HA_HW + akq * 4) =
                    make_uint2(*(uint32_t*)&h01, *(uint32_t*)&h23);
                #pragma unroll
                for (int r = 0; r < 4; r++) {
                    int k2 = bkb + r * 4;
                    __half2 p0 = __floats2half2_rn(bRa[r].x, bRb[r].x);
                    __half2 p1 = __floats2half2_rn(bRa[r].y, bRb[r].y);
                    __half2 p2 = __floats2half2_rn(bRa[r].z, bRb[r].z);
                    __half2 p3 = __floats2half2_rn(bRa[r].w, bRb[r].w);
                    uint32_t* d = BN + k2 * HB_W + bn4 * 4;
                    d[0] = *(uint32_t*)&p0; d[1] = *(uint32_t*)&p1;
                    d[2] = *(uint32_t*)&p2; d[3] = *(uint32_t*)&p3;
                }
                __syncthreads();
            }
        }

        // epilogue: write fp32 h_loc
        #pragma unroll
        for (int mt = 0; mt < 2; mt++) {
            int row0 = j0 + mt * 16 + g;
            #pragma unroll
            for (int nt = 0; nt < 4; nt++) {
                int ncol = n0w + nt * 8 + 2 * tig;
                *(float2*)&g_hloc[(size_t)row0 * HIDN + ncol] =
                    make_float2(acc[mt][nt][0], acc[mt][nt][1]);
                *(float2*)&g_hloc[(size_t)(row0 + 8) * HIDN + ncol] =
                    make_float2(acc[mt][nt][2], acc[mt][nt][3]);
            }
        }
    } else if (bx < 452) {
        // ================= h_glb =================
        float* red = dsm;                    // 256 floats
        const int bb  = bx - 196;
        const int i   = bb >> 3;
        const int o0  = (bb & 7) * 32;
        const int o   = o0 + (tid & 31);
        const int kq  = tid >> 5;            // 0..7
        const float* g = gf + i * DGLB + kq * 256;
        const float* w = W1 + (size_t)(kq * 256) * HIDN + o;
        float s0 = 0.f, s1 = 0.f;
        #pragma unroll 8
        for (int k = 0; k < 256; k += 2) {
            s0 += g[k]     * w[(size_t)k * HIDN];
            s1 += g[k + 1] * w[(size_t)(k + 1) * HIDN];
        }
        red[tid] = s0 + s1;
        __syncthreads();
        if (tid < 32) {
            float s = 0.f;
            #pragma unroll
            for (int q = 0; q < 8; q++) s += red[q * 32 + tid];
            g_hglb[i * HIDN + o0 + tid] = s + b1[o0 + tid];
        }
    } else {
        // ================= W2 fragment pack =================
        const int pid0 = ((bx - 452) * 256 + tid) * 8;
        #pragma unroll
        for (int q = 0; q < 8; q++) {
            int id   = pid0 + q;
            int lane = id & 31;
            int nt   = (id >> 5) & 7;
            int nwp  = (id >> 8) & 3;
            int ks   = id >> 10;
            int gq   = lane >> 2, tg = lane & 3;
            int n    = nwp * 64 + nt * 8 + gq;
            int k0   = ks * 16 + 2 * tg;
            __half2 w0 = __floats2half2_rn(W2[(size_t)k0 * HIDN + n],
                                           W2[(size_t)(k0 + 1) * HIDN + n]);
            __half2 w1 = __floats2half2_rn(W2[(size_t)(k0 + 8) * HIDN + n],
                                           W2[(size_t)(k0 + 9) * HIDN + n]);
            g_W2f[id] = make_uint2(*(uint32_t*)&w0, *(uint32_t*)&w1);
        }
    }
}

// ---------------------------------------------------------------------------
// PERSISTENT score kernel (UNCHANGED from R12/R13): 148 CTAs, 512 threads.
// ---------------------------------------------------------------------------
#define AS_STRH  72                                 // halves per A row (36 words)
#define AS_BYTES (128 * AS_STRH * 2)                // 18432
#define BCHUNK   32768
#define AS_OFF   0
#define BS_OFF   (2 * AS_BYTES)                     // 36864
#define B2_OFF   (BS_OFF + 4 * BCHUNK)              // 167936
#define W3_OFF   (B2_OFF + 1024)
#define RED_OFF  (W3_OFF + 1024)
#define SM_TOTAL (RED_OFF + 128 * 4 * 4)            // 172032

__global__ __launch_bounds__(512, 1) void score_mma(const float* __restrict__ b2,
                                                    const float* __restrict__ W3,
                                                    const float* __restrict__ b3p) {
    extern __shared__ char smem[];
    float* b2s = (float*)(smem + B2_OFF);
    float* w3s = (float*)(smem + W3_OFF);
    float* red = (float*)(smem + RED_OFF);
    const uint32_t sbase = smem_u32(smem);

    const int tid = threadIdx.x;
    const int wid = tid >> 5, lid = tid & 31;
    const int g   = lid >> 2, tig = lid & 3;
    const int m0w = (wid & 3) * 32;
    const int nw  = wid >> 2;
    const int n0w = nw * 64;

    {
        const char* bsrc = (const char*)g_W2f;
        #pragma unroll
        for (int cg2 = 0; cg2 < 4; cg2++) {
            #pragma unroll
            for (int r = 0; r < 4; r++) {
                int off = cg2 * BCHUNK + (tid + r * 512) * 16;
                cpa16(sbase + BS_OFF + off, bsrc + off);
            }
            CPA_COMMIT();
        }
    }

    if (tid < 256) { b2s[tid] = b2[tid]; w3s[tid] = W3[tid]; }
    const float b3v = b3p[0];

    const int k4   = tid & 15;
    const int mrow = tid >> 4;

    float acc[2][8][4];
    #pragma unroll
    for (int mt = 0; mt < 2; mt++)
        #pragma unroll
        for (int nt = 0; nt < 8; nt++)
            #pragma unroll
            for (int q = 0; q < 4; q++) acc[mt][nt][q] = 0.f;

    {
        const int t0 = blockIdx.x;
        const float* hl = g_hloc + (size_t)(t0 % NJT) * 128 * HIDN;
        const float* gb = g_hglb + (t0 / NJT) * HIDN;
        float4 gv = *(const float4*)(gb + k4 * 4);
        __half* As0 = (__half*)(smem + AS_OFF);
        #pragma unroll
        for (int r = 0; r < 4; r++) {
            int m = mrow + r * 32;
            float4 v = *(const float4*)(hl + (size_t)m * HIDN + k4 * 4);
            __half2 h01 = __floats2half2_rn(fmaxf(v.x + gv.x, 0.f), fmaxf(v.y + gv.y, 0.f));
            __half2 h23 = __floats2half2_rn(fmaxf(v.z + gv.z, 0.f), fmaxf(v.w + gv.w, 0.f));
            *(uint2*)(As0 + m * AS_STRH + k4 * 4) =
                make_uint2(*(uint32_t*)&h01, *(uint32_t*)&h23);
        }
        asm volatile("cp.async.wait_group 3;" ::: "memory");
        __syncthreads();
    }

    const uint2* BsP = (const uint2*)(smem + BS_OFF);
    int cg = 0;

    for (int t = blockIdx.x; t < NTILE; t += NCTA) {
        const int jt = t % NJT, ii = t / NJT;

        for (int c = 0; c < 4; c++) {
            const int pb = cg & 1, nb = pb ^ 1;
            const uint32_t* AsU = (const uint32_t*)(smem + AS_OFF + pb * AS_BYTES);

            const bool hn = (c < 3) || (t + NCTA < NTILE);
            float4 areg[4];
            float4 gvn;
            if (hn) {
                const int t2 = (c < 3) ? t : t + NCTA;
                const int c2 = (c < 3) ? c + 1 : 0;
                const float* hl2 = g_hloc + (size_t)(t2 % NJT) * 128 * HIDN;
                const float* gb2 = g_hglb + (t2 / NJT) * HIDN;
                const int kb2 = c2 * 64;
                gvn = *(const float4*)(gb2 + kb2 + k4 * 4);
                #pragma unroll
                for (int r = 0; r < 4; r++) {
                    int m = mrow + r * 32;
                    areg[r] = *(const float4*)(hl2 + (size_t)m * HIDN + kb2 + k4 * 4);
                }
            }

            #pragma unroll
            for (int kk = 0; kk < 4; kk++) {
                const int kw = kk * 8;
                const int ks = c * 4 + kk;
                uint32_t a[2][4];
                #pragma unroll
                for (int mt = 0; mt < 2; mt++) {
                    int mr = m0w + mt * 16 + g;
                    a[mt][0] = AsU[mr * 36 + kw + tig];
                    a[mt][1] = AsU[(mr + 8) * 36 + kw + tig];
                    a[mt][2] = AsU[mr * 36 + kw + tig + 4];
                    a[mt][3] = AsU[(mr + 8) * 36 + kw + tig + 4];
                }
                #pragma unroll
                for (int nt = 0; nt < 8; nt++) {
                    uint2 bw = BsP[((ks * 4 + nw) * 8 + nt) * 32 + lid];
                    mma16(acc[0][nt], a[0], bw.x, bw.y);
                    mma16(acc[1][nt], a[1], bw.x, bw.y);
                }
            }

            if (hn) {
                __half* AsN = (__half*)(smem + AS_OFF + nb * AS_BYTES);
                #pragma unroll
                for (int r = 0; r < 4; r++) {
                    int m = mrow + r * 32;
                    __half2 h01 = __floats2half2_rn(fmaxf(areg[r].x + gvn.x, 0.f),
                                                    fmaxf(areg[r].y + gvn.y, 0.f));
                    __half2 h23 = __floats2half2_rn(fmaxf(areg[r].z + gvn.z, 0.f),
                                                    fmaxf(areg[r].w + gvn.w, 0.f));
                    *(uint2*)(AsN + m * AS_STRH + k4 * 4) =
                        make_uint2(*(uint32_t*)&h01, *(uint32_t*)&h23);
                }
            }
            if (cg == 0)      asm volatile("cp.async.wait_group 2;" ::: "memory");
            else if (cg == 1) asm volatile("cp.async.wait_group 1;" ::: "memory");
            else if (cg == 2) asm volatile("cp.async.wait_group 0;" ::: "memory");
            __syncthreads();
            cg++;
        }

        #pragma unroll
        for (int mt = 0; mt < 2; mt++) {
            float s0 = 0.f, s1 = 0.f;
            #pragma unroll
            for (int nt = 0; nt < 8; nt++) {
                int n = n0w + nt * 8 + 2 * tig;
                float w0 = w3s[n], w1 = w3s[n + 1];
                float c0 = b2s[n], c1 = b2s[n + 1];
                s0 += fmaxf(acc[mt][nt][0] + c0, 0.f) * w0
                    + fmaxf(acc[mt][nt][1] + c1, 0.f) * w1;
                s1 += fmaxf(acc[mt][nt][2] + c0, 0.f) * w0
                    + fmaxf(acc[mt][nt][3] + c1, 0.f) * w1;
            }
            s0 += __shfl_xor_sync(0xffffffffu, s0, 1);
            s0 += __shfl_xor_sync(0xffffffffu, s0, 2);
            s1 += __shfl_xor_sync(0xffffffffu, s1, 1);
            s1 += __shfl_xor_sync(0xffffffffu, s1, 2);
            if (tig == 0) {
                red[(m0w + mt * 16 + g) * 4 + nw]     = s0;
                red[(m0w + mt * 16 + g + 8) * 4 + nw] = s1;
            }
        }
        #pragma unroll
        for (int mt = 0; mt < 2; mt++)
            #pragma unroll
            for (int nt = 0; nt < 8; nt++)
                #pragma unroll
                for (int q = 0; q < 4; q++) acc[mt][nt][q] = 0.f;
        __syncthreads();
        if (tid < 128) {
            float s = red[tid * 4] + red[tid * 4 + 1] + red[tid * 4 + 2] + red[tid * 4 + 3];
            g_scores[ii * NHW + jt * 128 + tid] = s + b3v;
        }
        __syncthreads();
    }
}

// ---------------------------------------------------------------------------
// finalize: register-cached row + shuffle reductions (2-stage)
// ---------------------------------------------------------------------------
__global__ __launch_bounds__(1024) void finalize_kernel(float* __restrict__ out) {
    const int i    = blockIdx.x;
    const int tid  = threadIdx.x;
    const int wid  = tid >> 5, lane = tid & 31;
    __shared__ float sred[32];
    __shared__ float sbc[2];
    const float* row = g_scores + i * NHW;

    float v[7];
    const bool has7 = (tid < NHW - 6 * 1024);
    float mx = -1e30f;
    #pragma unroll
    for (int k = 0; k < 6; k++) {
        v[k] = row[tid + k * 1024];
        mx = fmaxf(mx, v[k]);
    }
    if (has7) { v[6] = row[tid + 6 * 1024]; mx = fmaxf(mx, v[6]); }

    #pragma unroll
    for (int off = 16; off; off >>= 1)
        mx = fmaxf(mx, __shfl_xor_sync(0xffffffffu, mx, off));
    if (lane == 0) sred[wid] = mx;
    __syncthreads();
    if (wid == 0) {
        float m = sred[lane];
        #pragma unroll
        for (int off = 16; off; off >>= 1)
            m = fmaxf(m, __shfl_xor_sync(0xffffffffu, m, off));
        if (lane == 0) sbc[0] = m;
    }
    __syncthreads();
    mx = sbc[0];

    const int lo = i * HW2, hi = lo + HW2;
    float sum = 0.f;
    #pragma unroll
    for (int k = 0; k < 6; k++) {
        int jj = tid + k * 1024;
        if (jj < lo || jj >= hi) sum += __expf(v[k] - mx);
    }
    if (has7) {
        int jj = tid + 6 * 1024;
        if (jj < lo || jj >= hi) sum += __expf(v[6] - mx);
    }
    #pragma unroll
    for (int off = 16; off; off >>= 1)
        sum += __shfl_xor_sync(0xffffffffu, sum, off);
    if (lane == 0) sred[wid] = sum;
    __syncthreads();
    if (wid == 0) {
        float s = sred[lane];
        #pragma unroll
        for (int off = 16; off; off >>= 1)
            s += __shfl_xor_sync(0xffffffffu, s, off);
        if (lane == 0) sbc[1] = s;
    }
    __syncthreads();

    const float neg_mean = sbc[1] / (float)(NHW - HW2) + EPSC;
    const float lg = __logf(neg_mean);

    for (int p = tid; p < HW2; p += 1024)
        out[i * HW2 + p] = row[lo + p] - mx - lg;
}

// ---------------------------------------------------------------------------
extern "C" void kernel_launch(void* const* d_in, const int* in_sizes, int n_in,
                              void* d_out, int out_size) {
    const float* LF = (const float*)d_in[0];
    const float* GF = (const float*)d_in[1];
    const float* W1 = (const float*)d_in[2];
    const float* b1 = (const float*)d_in[3];
    const float* W2 = (const float*)d_in[4];
    const float* b2 = (const float*)d_in[5];
    const float* W3 = (const float*)d_in[6];
    const float* b3 = (const float*)d_in[7];
    float* out = (float*)d_out;

    cudaFuncSetAttribute(pre_kernel, cudaFuncAttributeMaxDynamicSharedMemorySize, PRE_SMEM);
    cudaFuncSetAttribute(score_mma, cudaFuncAttributeMaxDynamicSharedMemorySize, SM_TOTAL);

    pre_kernel<<<460, 256, PRE_SMEM>>>(LF, W1 + (size_t)DGLB * HIDN, GF, W1, b1, W2);
    score_mma<<<NCTA, 512, SM_TOTAL>>>(b2, W3, b3);
    finalize_kernel<<<NB, 1024>>>(out);
}